// round 1
// baseline (speedup 1.0000x reference)
#include <cuda_runtime.h>
#include <math.h>

#define Bn 8
#define NMELS 128
#define TIN 4096
#define T1 2048
#define S 1024
#define D 1024
#define H 8
#define DH 128
#define Fdim 4096
#define NTOK (Bn*S)

// ---------------- scratch (static device globals; no allocation) ----------------
__device__ float g_col[Bn*3072*S];                 // im2col buffer (reused), 100MB
__device__ float g_h1 [Bn*D*T1];                   // conv1 output (NCH), 67MB
__device__ float g_x  [NTOK*D];                    // residual stream [tok, D]
__device__ float g_y  [NTOK*D];                    // LN output
__device__ float g_q  [NTOK*D];
__device__ float g_k  [NTOK*D];
__device__ float g_v  [NTOK*D];
__device__ float g_o  [NTOK*D];
__device__ float g_mlp[(size_t)NTOK*Fdim];         // 128MB
__device__ float g_scores[(size_t)Bn*H*S*S];       // 256MB

// ---------------- generic fp32 SGEMM: C = A * op(B), fused epilogue ----------------
// A: MxK row-major (lda). B: NN -> KxN row-major (ldb); NT -> W[N,K] row-major (ldb).
// batch offset for operand P: (z/zDiv)*sPo + (z%zDiv)*sPi
struct GemmP {
    const float* A; const float* B; float* C;
    const float* bias;
    int M, N, K, lda, ldb, ldc;
    int zDiv;
    long long sAo, sAi, sBo, sBi, sCo, sCi;
    int transB;     // 0: NN, 1: NT
    int biasMode;   // 0 none, 1 per-col(N), 2 per-row(M)
    int addC;       // accumulate into existing C (residual)
    int act;        // 0 none, 1 exact GELU
    int transStore; // store element (m,n) at C[n*ldc + m]
};

__device__ __forceinline__ float gelu_exact(float v) {
    return 0.5f * v * (1.0f + erff(v * 0.70710678118654752f));
}

__global__ __launch_bounds__(256) void gemm_k(GemmP p) {
    __shared__ __align__(16) float As[8][128];
    __shared__ __align__(16) float Bs[8][128];

    int z = blockIdx.z;
    const float* A  = p.A + (long long)(z / p.zDiv) * p.sAo + (long long)(z % p.zDiv) * p.sAi;
    const float* Bm = p.B + (long long)(z / p.zDiv) * p.sBo + (long long)(z % p.zDiv) * p.sBi;
    float*       C  = p.C + (long long)(z / p.zDiv) * p.sCo + (long long)(z % p.zDiv) * p.sCi;

    int n0 = blockIdx.x * 128, m0 = blockIdx.y * 128;
    int tid = threadIdx.x;
    int tx = tid & 15, ty = tid >> 4;

    float acc[8][8];
    #pragma unroll
    for (int i = 0; i < 8; i++)
        #pragma unroll
        for (int j = 0; j < 8; j++) acc[i][j] = 0.f;

    int aRow   = tid >> 1,  aCol   = (tid & 1) * 4;   // 128 rows x 8 cols, float4
    int bRowNN = tid >> 5,  bColNN = (tid & 31) * 4;  // 8 rows x 128 cols, float4

    for (int k0 = 0; k0 < p.K; k0 += 8) {
        float4 av = *(const float4*)&A[(long long)(m0 + aRow) * p.lda + k0 + aCol];
        As[aCol + 0][aRow] = av.x; As[aCol + 1][aRow] = av.y;
        As[aCol + 2][aRow] = av.z; As[aCol + 3][aRow] = av.w;
        if (p.transB) {
            float4 bv = *(const float4*)&Bm[(long long)(n0 + aRow) * p.ldb + k0 + aCol];
            Bs[aCol + 0][aRow] = bv.x; Bs[aCol + 1][aRow] = bv.y;
            Bs[aCol + 2][aRow] = bv.z; Bs[aCol + 3][aRow] = bv.w;
        } else {
            float4 bv = *(const float4*)&Bm[(long long)(k0 + bRowNN) * p.ldb + n0 + bColNN];
            *(float4*)&Bs[bRowNN][bColNN] = bv;
        }
        __syncthreads();
        #pragma unroll
        for (int kk = 0; kk < 8; kk++) {
            float a[8], b[8];
            *(float4*)&a[0] = *(const float4*)&As[kk][ty * 8];
            *(float4*)&a[4] = *(const float4*)&As[kk][ty * 8 + 4];
            *(float4*)&b[0] = *(const float4*)&Bs[kk][tx * 8];
            *(float4*)&b[4] = *(const float4*)&Bs[kk][tx * 8 + 4];
            #pragma unroll
            for (int i = 0; i < 8; i++)
                #pragma unroll
                for (int j = 0; j < 8; j++) acc[i][j] += a[i] * b[j];
        }
        __syncthreads();
    }

    #pragma unroll
    for (int i = 0; i < 8; i++) {
        int m = m0 + ty * 8 + i;
        #pragma unroll
        for (int j = 0; j < 8; j++) {
            int n = n0 + tx * 8 + j;
            float v = acc[i][j];
            if (p.biasMode == 1) v += p.bias[n];
            else if (p.biasMode == 2) v += p.bias[m];
            if (p.act == 1) v = gelu_exact(v);
            long long off = p.transStore ? ((long long)n * p.ldc + m)
                                         : ((long long)m * p.ldc + n);
            if (p.addC) v += C[off];
            C[off] = v;
        }
    }
}

// ---------------- im2col ----------------
__global__ void im2col1_k(const float* __restrict__ x) {
    int idx = blockIdx.x * 256 + threadIdx.x;
    const int total = Bn * 384 * T1;
    if (idx >= total) return;
    int t = idx % T1;
    int r = (idx / T1) % 384;
    int b = idx / (T1 * 384);
    int i = r / 3, kk = r % 3;
    int pos = 2 * t + kk - 1;
    float v = (pos >= 0 && pos < TIN) ? x[((long long)b * NMELS + i) * TIN + pos] : 0.f;
    g_col[idx] = v;
}

__global__ void im2col2_k() {
    long long idx = (long long)blockIdx.x * 256 + threadIdx.x;
    const long long total = (long long)Bn * 3072 * S;
    if (idx >= total) return;
    int t = (int)(idx % S);
    int r = (int)((idx / S) % 3072);
    int b = (int)(idx / ((long long)S * 3072));
    int i = r / 3, kk = r % 3;
    int pos = 2 * t + kk - 1;
    float v = (pos >= 0 && pos < T1) ? g_h1[((long long)b * D + i) * T1 + pos] : 0.f;
    g_col[idx] = v;
}

// ---------------- LayerNorm (row = token, width 1024) ----------------
__global__ void ln_k(const float* __restrict__ x, float* __restrict__ y,
                     const float* __restrict__ w, const float* __restrict__ b) {
    int row = blockIdx.x;
    int tid = threadIdx.x;
    const float* xr = x + (long long)row * D;
    __shared__ float red[256];
    float v[4];
    #pragma unroll
    for (int i = 0; i < 4; i++) v[i] = xr[tid + 256 * i];
    float s = v[0] + v[1] + v[2] + v[3];
    red[tid] = s; __syncthreads();
    for (int o = 128; o > 0; o >>= 1) { if (tid < o) red[tid] += red[tid + o]; __syncthreads(); }
    float mean = red[0] * (1.f / D);
    __syncthreads();
    float sq = 0.f;
    #pragma unroll
    for (int i = 0; i < 4; i++) { float d0 = v[i] - mean; sq += d0 * d0; }
    red[tid] = sq; __syncthreads();
    for (int o = 128; o > 0; o >>= 1) { if (tid < o) red[tid] += red[tid + o]; __syncthreads(); }
    float rstd = rsqrtf(red[0] * (1.f / D) + 1e-5f);
    #pragma unroll
    for (int i = 0; i < 4; i++) {
        int c = tid + 256 * i;
        y[(long long)row * D + c] = (v[i] - mean) * rstd * w[c] + b[c];
    }
}

// ---------------- RoPE + scale on q,k ----------------
__global__ void rope_k() {
    int idx = blockIdx.x * 256 + threadIdx.x;
    if (idx >= NTOK * (D / 2)) return;
    int tok = idx / (D / 2);
    int p   = idx % (D / 2);
    int h = p >> 6;
    int j = p & 63;
    int s = tok & (S - 1);
    float freq = powf(10000.f, -(float)(2 * j) * (1.f / 128.f));
    float ang = (float)s * freq;
    float c, sn; sincosf(ang, &sn, &c);
    const float sc = 0.29730177875068026f;  // 128^-0.25
    long long base = (long long)tok * D + h * 128 + 2 * j;
    float qr = g_q[base], qi = g_q[base + 1];
    g_q[base]     = (qr * c - qi * sn) * sc;
    g_q[base + 1] = (qr * sn + qi * c) * sc;
    float kr = g_k[base], ki = g_k[base + 1];
    g_k[base]     = (kr * c - ki * sn) * sc;
    g_k[base + 1] = (kr * sn + ki * c) * sc;
}

// ---------------- masked softmax over key dim (row length S) ----------------
__global__ void softmax_k(const int* __restrict__ x_len) {
    long long row = blockIdx.x;                 // B*H*S rows
    int b = (int)(row >> 13);                   // row / (H*S)
    float* r = g_scores + row * S;
    int tid = threadIdx.x;
    int xl = x_len[b];
    __shared__ float red[256];
    float v[4];
    #pragma unroll
    for (int i = 0; i < 4; i++) {
        int j = tid + 256 * i;
        float bias = (4 * j + 3 < xl) ? 0.f : -1e10f;
        v[i] = r[j] + bias;
    }
    float m = fmaxf(fmaxf(v[0], v[1]), fmaxf(v[2], v[3]));
    red[tid] = m; __syncthreads();
    for (int o = 128; o > 0; o >>= 1) { if (tid < o) red[tid] = fmaxf(red[tid], red[tid + o]); __syncthreads(); }
    m = red[0]; __syncthreads();
    float s = 0.f;
    #pragma unroll
    for (int i = 0; i < 4; i++) { v[i] = expf(v[i] - m); s += v[i]; }
    red[tid] = s; __syncthreads();
    for (int o = 128; o > 0; o >>= 1) { if (tid < o) red[tid] += red[tid + o]; __syncthreads(); }
    float inv = 1.f / red[0];
    #pragma unroll
    for (int i = 0; i < 4; i++) r[tid + 256 * i] = v[i] * inv;
}

// ---------------- output: h then y_len (as float) ----------------
__global__ void out_k(float* __restrict__ out, const int* __restrict__ x_len, long long out_size) {
    long long i = (long long)blockIdx.x * 256 + threadIdx.x;
    const long long nh = (long long)NTOK * D;
    if (i < nh && i < out_size) out[i] = g_x[i];
    if (i < Bn) {
        long long pos = nh + i;
        if (pos < out_size) {
            int yl = (x_len[i] + 1) / 2;
            yl = (yl + 1) / 2;
            out[pos] = (float)yl;
        }
    }
}

// ---------------- host launcher ----------------
extern "C" void kernel_launch(void* const* d_in, const int* in_sizes, int n_in,
                              void* d_out, int out_size) {
    const float* x        = (const float*)d_in[0];
    const int*   x_len    = (const int*)  d_in[1];
    const float* conv1_w  = (const float*)d_in[2];
    const float* conv1_b  = (const float*)d_in[3];
    const float* conv2_w  = (const float*)d_in[4];
    const float* conv2_b  = (const float*)d_in[5];
    const float* attn_ln_w= (const float*)d_in[6];
    const float* attn_ln_b= (const float*)d_in[7];
    const float* q_w      = (const float*)d_in[8];
    const float* q_b      = (const float*)d_in[9];
    const float* k_w      = (const float*)d_in[10];
    const float* v_w      = (const float*)d_in[11];
    const float* v_b      = (const float*)d_in[12];
    const float* out_w    = (const float*)d_in[13];
    const float* out_b    = (const float*)d_in[14];
    const float* mlp_ln_w = (const float*)d_in[15];
    const float* mlp_ln_b = (const float*)d_in[16];
    const float* mlp1_w   = (const float*)d_in[17];
    const float* mlp1_b   = (const float*)d_in[18];
    const float* mlp2_w   = (const float*)d_in[19];
    const float* mlp2_b   = (const float*)d_in[20];

    float *col, *h1, *xs, *ys, *qs, *ks, *vs, *os, *mlp, *sc;
    cudaGetSymbolAddress((void**)&col, g_col);
    cudaGetSymbolAddress((void**)&h1,  g_h1);
    cudaGetSymbolAddress((void**)&xs,  g_x);
    cudaGetSymbolAddress((void**)&ys,  g_y);
    cudaGetSymbolAddress((void**)&qs,  g_q);
    cudaGetSymbolAddress((void**)&ks,  g_k);
    cudaGetSymbolAddress((void**)&vs,  g_v);
    cudaGetSymbolAddress((void**)&os,  g_o);
    cudaGetSymbolAddress((void**)&mlp, g_mlp);
    cudaGetSymbolAddress((void**)&sc,  g_scores);

    auto gemm = [&](const float* A, const float* B, float* C, const float* bias,
                    int M, int N, int K, int lda, int ldb, int ldc,
                    int nz, int zDiv,
                    long long sAo, long long sAi, long long sBo, long long sBi,
                    long long sCo, long long sCi,
                    int transB, int biasMode, int addC, int act, int transStore) {
        GemmP p;
        p.A = A; p.B = B; p.C = C; p.bias = bias;
        p.M = M; p.N = N; p.K = K; p.lda = lda; p.ldb = ldb; p.ldc = ldc;
        p.zDiv = zDiv;
        p.sAo = sAo; p.sAi = sAi; p.sBo = sBo; p.sBi = sBi; p.sCo = sCo; p.sCi = sCi;
        p.transB = transB; p.biasMode = biasMode; p.addC = addC; p.act = act;
        p.transStore = transStore;
        dim3 g(N / 128, M / 128, nz);
        gemm_k<<<g, 256>>>(p);
    };

    const long long SD = (long long)S * D;         // 1048576
    const long long SS = (long long)S * S;         // 1048576

    // conv1: im2col + GEMM [1024 x 2048] = W1[1024,384] * col[384,2048], bias/row, GELU
    im2col1_k<<<(Bn * 384 * T1 + 255) / 256, 256>>>(x);
    gemm(conv1_w, col, h1, conv1_b,
         1024, T1, 384, 384, T1, T1,
         Bn, 1, 0, 0, (long long)384 * T1, 0, (long long)D * T1, 0,
         0, 2, 0, 1, 0);

    // conv2: im2col + GEMM [1024 x 1024] = W2[1024,3072] * col[3072,1024], GELU, store transposed -> g_x [tok, D]
    im2col2_k<<<(int)(((long long)Bn * 3072 * S + 255) / 256), 256>>>();
    gemm(conv2_w, col, xs, conv2_b,
         1024, S, 3072, 3072, S, D,
         Bn, 1, 0, 0, (long long)3072 * S, 0, SD, 0,
         0, 2, 0, 1, 1);

    for (int l = 0; l < 6; l++) {
        const float* aw = attn_ln_w + l * D;  const float* ab = attn_ln_b + l * D;
        const float* qw = q_w + (long long)l * D * D;  const float* qb = q_b + l * D;
        const float* kw = k_w + (long long)l * D * D;
        const float* vw = v_w + (long long)l * D * D;  const float* vb = v_b + l * D;
        const float* ow = out_w + (long long)l * D * D; const float* ob = out_b + l * D;
        const float* mw = mlp_ln_w + l * D;   const float* mb = mlp_ln_b + l * D;
        const float* w1 = mlp1_w + (long long)l * Fdim * D; const float* b1 = mlp1_b + l * Fdim;
        const float* w2 = mlp2_w + (long long)l * D * Fdim; const float* b2 = mlp2_b + l * D;

        // attn LN
        ln_k<<<NTOK, 256>>>(xs, ys, aw, ab);

        // q,k,v projections (NT)
        gemm(ys, qw, qs, qb, NTOK, D, D, D, D, D, 1, 1, 0,0,0,0,0,0, 1, 1, 0, 0, 0);
        gemm(ys, kw, ks, 0,  NTOK, D, D, D, D, D, 1, 1, 0,0,0,0,0,0, 1, 0, 0, 0, 0);
        gemm(ys, vw, vs, vb, NTOK, D, D, D, D, D, 1, 1, 0,0,0,0,0,0, 1, 1, 0, 0, 0);

        // RoPE + scale on q,k
        rope_k<<<(NTOK * (D / 2) + 255) / 256, 256>>>();

        // scores[b,h] = q_bh (S x 128) * k_bh^T  -> g_scores
        gemm(qs, ks, sc, 0,
             S, S, DH, D, D, S,
             Bn * H, H, SD, 128, SD, 128, (long long)H * SS, SS,
             1, 0, 0, 0, 0);

        // masked softmax
        softmax_k<<<Bn * H * S, 256>>>(x_len);

        // o[b,h] = softmax (S x S) * v_bh (S x 128)
        gemm(sc, vs, os, 0,
             S, DH, S, S, D, D,
             Bn * H, H, (long long)H * SS, SS, SD, 128, SD, 128,
             0, 0, 0, 0, 0);

        // out projection + residual into g_x
        gemm(os, ow, xs, ob, NTOK, D, D, D, D, D, 1, 1, 0,0,0,0,0,0, 1, 1, 1, 0, 0);

        // MLP
        ln_k<<<NTOK, 256>>>(xs, ys, mw, mb);
        gemm(ys, w1, mlp, b1, NTOK, Fdim, D, D, D, Fdim, 1, 1, 0,0,0,0,0,0, 1, 1, 0, 1, 0);
        gemm(mlp, w2, xs, b2, NTOK, D, Fdim, Fdim, Fdim, D, 1, 1, 0,0,0,0,0,0, 1, 1, 1, 0, 0);
    }

    // write h and y_len
    long long nh = (long long)NTOK * D;
    out_k<<<(int)((nh + 255) / 256), 256>>>((float*)d_out, x_len, (long long)out_size);
}

// round 2
// speedup vs baseline: 2.1218x; 2.1218x over previous
#include <cuda_runtime.h>
#include <cuda_bf16.h>
#include <math.h>

typedef __nv_bfloat16 bf16;
typedef long long ll;

#define Bn 8
#define NMELS 128
#define TIN 4096
#define T1 2048
#define S 1024
#define D 1024
#define H 8
#define DH 128
#define Fdim 4096
#define NTOK (Bn*S)
#define Ldim 6

// ---------------- fp32 scratch ----------------
__device__ float g_h1[(size_t)Bn*D*T1];
__device__ float g_x [(size_t)NTOK*D];
__device__ float g_q [(size_t)NTOK*D];
__device__ float g_k [(size_t)NTOK*D];
__device__ float g_scores[(size_t)Bn*H*S*S];

// ---------------- bf16 hi/lo buffers ----------------
__device__ bf16 c1h[(size_t)D*384],  c1l[(size_t)D*384];
__device__ bf16 c2h[(size_t)D*3072], c2l[(size_t)D*3072];
__device__ bf16 wqh[(size_t)Ldim*D*D], wql[(size_t)Ldim*D*D];
__device__ bf16 wkh[(size_t)Ldim*D*D], wkl[(size_t)Ldim*D*D];
__device__ bf16 wvh[(size_t)Ldim*D*D], wvl[(size_t)Ldim*D*D];
__device__ bf16 woh[(size_t)Ldim*D*D], wol[(size_t)Ldim*D*D];
__device__ bf16 w1h[(size_t)Ldim*Fdim*D], w1l[(size_t)Ldim*Fdim*D];
__device__ bf16 w2h[(size_t)Ldim*Fdim*D], w2l[(size_t)Ldim*Fdim*D];
__device__ bf16 g_colh[(size_t)Bn*3072*S], g_coll[(size_t)Bn*3072*S];
__device__ bf16 g_yh[(size_t)NTOK*D], g_yl[(size_t)NTOK*D];
__device__ bf16 g_qh[(size_t)NTOK*D], g_ql[(size_t)NTOK*D];
__device__ bf16 g_kh[(size_t)NTOK*D], g_kl[(size_t)NTOK*D];
__device__ bf16 g_vth[(size_t)D*NTOK], g_vtl[(size_t)D*NTOK];
__device__ bf16 g_ph[(size_t)Bn*H*S*S], g_pl[(size_t)Bn*H*S*S];
__device__ bf16 g_m1h[(size_t)NTOK*Fdim], g_m1l[(size_t)NTOK*Fdim];
__device__ bf16 g_oh[(size_t)NTOK*D], g_ol[(size_t)NTOK*D];

// ---------------- helpers ----------------
__device__ __forceinline__ float gelu_exact(float v) {
    return 0.5f * v * (1.0f + erff(v * 0.70710678118654752f));
}
__device__ __forceinline__ void splitf(float v, bf16& h, bf16& l) {
    h = __float2bfloat16_rn(v);
    l = __float2bfloat16_rn(v - __bfloat162float(h));
}
__device__ __forceinline__ void mma_bf16(float* d, const unsigned* a, const unsigned* b) {
    asm volatile(
        "mma.sync.aligned.m16n8k16.row.col.f32.bf16.bf16.f32 "
        "{%0,%1,%2,%3}, {%4,%5,%6,%7}, {%8,%9}, {%0,%1,%2,%3};\n"
        : "+f"(d[0]), "+f"(d[1]), "+f"(d[2]), "+f"(d[3])
        : "r"(a[0]), "r"(a[1]), "r"(a[2]), "r"(a[3]), "r"(b[0]), "r"(b[1]));
}
__device__ __forceinline__ void ldsm4(unsigned* r, unsigned addr) {
    asm volatile("ldmatrix.sync.aligned.m8n8.x4.shared.b16 {%0,%1,%2,%3}, [%4];\n"
        : "=r"(r[0]), "=r"(r[1]), "=r"(r[2]), "=r"(r[3]) : "r"(addr));
}
__device__ __forceinline__ void cpa16(unsigned dst, const void* src) {
    asm volatile("cp.async.cg.shared.global [%0], [%1], 16;\n" :: "r"(dst), "l"(src));
}

// ---------------- bf16x3 tensor-core GEMM ----------------
// C[M,N] = A[M,K] * B[N,K]^T ; A,B as bf16 hi/lo pairs.
#define KC 32
#define PAD 40
#define TILE_E (128*PAD)             // elems per smem tile
#define STG_B  (4*TILE_E*2)          // bytes per stage (Ah,Al,Bh,Bl)

struct GemmP {
    const bf16 *Ah, *Al, *Bh, *Bl;
    float* C; bf16 *Ch, *Cl;
    const float* bias;
    int K, lda, ldb, ldc;
    int zDiv;
    ll sAo, sAi, sBo, sBi, sCo, sCi;
    int biasMode;   // 0 none, 1 per-col(n), 2 per-row(m)
    int addC;       // fp32 residual accumulate
    int act;        // exact GELU
    int transStore; // store (m,n) at [n*ldc+m]
    int outF32, outBf;
};

__global__ __launch_bounds__(256, 1) void gemm_tc(GemmP p) {
    extern __shared__ __align__(16) bf16 sm[];
    int z = blockIdx.z;
    ll offA = (ll)(z / p.zDiv) * p.sAo + (ll)(z % p.zDiv) * p.sAi;
    ll offB = (ll)(z / p.zDiv) * p.sBo + (ll)(z % p.zDiv) * p.sBi;
    ll offC = (ll)(z / p.zDiv) * p.sCo + (ll)(z % p.zDiv) * p.sCi;
    const bf16* Ah = p.Ah + offA; const bf16* Al = p.Al + offA;
    const bf16* Bh = p.Bh + offB; const bf16* Bl = p.Bl + offB;

    int m0 = blockIdx.y * 128, n0 = blockIdx.x * 128;
    int tid = threadIdx.x, lane = tid & 31, wid = tid >> 5;
    int wm = (wid & 3) * 32, wn = (wid >> 2) * 64;
    unsigned smu = (unsigned)__cvta_generic_to_shared(sm);

    float acc[2][8][4];
    #pragma unroll
    for (int a = 0; a < 2; a++)
        #pragma unroll
        for (int b = 0; b < 8; b++)
            #pragma unroll
            for (int c = 0; c < 4; c++) acc[a][b][c] = 0.f;

    int ldRow = tid >> 2;       // 0..63
    int ldC   = tid & 3;        // 0..3 (16B chunk)

    // ---- issue one chunk into stage stg ----
    auto issue = [&](int k0, int stg) {
        unsigned base = smu + (unsigned)stg * STG_B;
        #pragma unroll
        for (int hh = 0; hh < 2; hh++) {
            int row = ldRow + hh * 64;
            unsigned so = (unsigned)(row * PAD + ldC * 8) * 2;
            cpa16(base + 0 * TILE_E * 2 + so, Ah + (ll)(m0 + row) * p.lda + k0 + ldC * 8);
            cpa16(base + 1 * TILE_E * 2 + so, Al + (ll)(m0 + row) * p.lda + k0 + ldC * 8);
            cpa16(base + 2 * TILE_E * 2 + so, Bh + (ll)(n0 + row) * p.ldb + k0 + ldC * 8);
            cpa16(base + 3 * TILE_E * 2 + so, Bl + (ll)(n0 + row) * p.ldb + k0 + ldC * 8);
        }
        asm volatile("cp.async.commit_group;\n" ::: "memory");
    };

    int nch = p.K / KC;
    issue(0, 0);
    int cur = 0;

    for (int c = 0; c < nch; c++) {
        asm volatile("cp.async.wait_group 0;\n" ::: "memory");
        __syncthreads();
        if (c + 1 < nch) issue((c + 1) * KC, cur ^ 1);

        unsigned aB  = smu + (unsigned)cur * STG_B;
        unsigned alB = aB + TILE_E * 2;
        unsigned bB  = aB + 2 * TILE_E * 2;
        unsigned blB = aB + 3 * TILE_E * 2;

        #pragma unroll
        for (int ks = 0; ks < 2; ks++) {
            unsigned ah[2][4], al[2][4], bh[8][2], bl[8][2];
            #pragma unroll
            for (int mi = 0; mi < 2; mi++) {
                int row = wm + mi * 16 + (lane & 15);
                int col = ks * 16 + (lane >> 4) * 8;
                unsigned off = (unsigned)(row * PAD + col) * 2;
                ldsm4(ah[mi], aB + off);
                ldsm4(al[mi], alB + off);
            }
            #pragma unroll
            for (int nj = 0; nj < 4; nj++) {
                int g = lane >> 3;
                int row = wn + nj * 16 + ((g >> 1) << 3) + (lane & 7);
                int col = ks * 16 + ((g & 1) << 3);
                unsigned off = (unsigned)(row * PAD + col) * 2;
                unsigned t[4];
                ldsm4(t, bB + off);
                bh[nj*2][0] = t[0]; bh[nj*2][1] = t[1];
                bh[nj*2+1][0] = t[2]; bh[nj*2+1][1] = t[3];
                ldsm4(t, blB + off);
                bl[nj*2][0] = t[0]; bl[nj*2][1] = t[1];
                bl[nj*2+1][0] = t[2]; bl[nj*2+1][1] = t[3];
            }
            #pragma unroll
            for (int mi = 0; mi < 2; mi++)
                #pragma unroll
                for (int nf = 0; nf < 8; nf++) {
                    mma_bf16(acc[mi][nf], ah[mi], bh[nf]);
                    mma_bf16(acc[mi][nf], ah[mi], bl[nf]);
                    mma_bf16(acc[mi][nf], al[mi], bh[nf]);
                }
        }
        cur ^= 1;
    }

    // ---- epilogue ----
    float* Cp = p.C + offC;
    bf16* Chp = p.Ch ? p.Ch + offC : nullptr;
    bf16* Clp = p.Cl ? p.Cl + offC : nullptr;
    #pragma unroll
    for (int mi = 0; mi < 2; mi++)
        #pragma unroll
        for (int nf = 0; nf < 8; nf++) {
            int rB = m0 + wm + mi * 16 + (lane >> 2);
            int cB = n0 + wn + nf * 8 + (lane & 3) * 2;
            #pragma unroll
            for (int e = 0; e < 4; e++) {
                int m = rB + (e >> 1) * 8;
                int n = cB + (e & 1);
                float v = acc[mi][nf][e];
                if (p.biasMode == 1) v += p.bias[n];
                else if (p.biasMode == 2) v += p.bias[m];
                if (p.act) v = gelu_exact(v);
                ll off = p.transStore ? ((ll)n * p.ldc + m) : ((ll)m * p.ldc + n);
                if (p.outF32) {
                    float vv = v;
                    if (p.addC) vv += Cp[off];
                    Cp[off] = vv;
                }
                if (p.outBf) {
                    bf16 h, l; splitf(v, h, l);
                    Chp[off] = h; Clp[off] = l;
                }
            }
        }
}

// ---------------- weight split ----------------
__global__ void split_k(const float* __restrict__ in, bf16* __restrict__ hi,
                        bf16* __restrict__ lo, ll n) {
    ll i = ((ll)blockIdx.x * 256 + threadIdx.x) * 4;
    if (i >= n) return;
    float4 v = *(const float4*)&in[i];
    bf16 h, l;
    splitf(v.x, h, l); hi[i+0] = h; lo[i+0] = l;
    splitf(v.y, h, l); hi[i+1] = h; lo[i+1] = l;
    splitf(v.z, h, l); hi[i+2] = h; lo[i+2] = l;
    splitf(v.w, h, l); hi[i+3] = h; lo[i+3] = l;
}

// ---------------- im2col (layout [b][t][r], r contiguous) ----------------
__global__ void im2col1_k(const float* __restrict__ x) {
    int idx = blockIdx.x * 256 + threadIdx.x;
    const int total = Bn * T1 * 384;
    if (idx >= total) return;
    int r = idx % 384;
    int t = (idx / 384) % T1;
    int b = idx / (384 * T1);
    int i = r / 3, kk = r % 3;
    int pos = 2 * t + kk - 1;
    float v = (pos >= 0 && pos < TIN) ? x[((ll)b * NMELS + i) * TIN + pos] : 0.f;
    bf16 h, l; splitf(v, h, l);
    g_colh[idx] = h; g_coll[idx] = l;
}
__global__ void im2col2_k() {
    ll idx = (ll)blockIdx.x * 256 + threadIdx.x;
    const ll total = (ll)Bn * S * 3072;
    if (idx >= total) return;
    int r = (int)(idx % 3072);
    int t = (int)((idx / 3072) % S);
    int b = (int)(idx / ((ll)S * 3072));
    int i = r / 3, kk = r % 3;
    int pos = 2 * t + kk - 1;
    float v = (pos >= 0 && pos < T1) ? g_h1[((ll)b * D + i) * T1 + pos] : 0.f;
    bf16 h, l; splitf(v, h, l);
    g_colh[idx] = h; g_coll[idx] = l;
}

// ---------------- LayerNorm -> bf16 hi/lo ----------------
__global__ void ln_k(const float* __restrict__ x,
                     const float* __restrict__ w, const float* __restrict__ b) {
    int row = blockIdx.x;
    int tid = threadIdx.x;
    const float* xr = x + (ll)row * D;
    __shared__ float red[256];
    float v[4];
    #pragma unroll
    for (int i = 0; i < 4; i++) v[i] = xr[tid + 256 * i];
    float s = v[0] + v[1] + v[2] + v[3];
    red[tid] = s; __syncthreads();
    for (int o = 128; o > 0; o >>= 1) { if (tid < o) red[tid] += red[tid + o]; __syncthreads(); }
    float mean = red[0] * (1.f / D);
    __syncthreads();
    float sq = 0.f;
    #pragma unroll
    for (int i = 0; i < 4; i++) { float d0 = v[i] - mean; sq += d0 * d0; }
    red[tid] = sq; __syncthreads();
    for (int o = 128; o > 0; o >>= 1) { if (tid < o) red[tid] += red[tid + o]; __syncthreads(); }
    float rstd = rsqrtf(red[0] * (1.f / D) + 1e-5f);
    #pragma unroll
    for (int i = 0; i < 4; i++) {
        int c = tid + 256 * i;
        float y = (v[i] - mean) * rstd * w[c] + b[c];
        bf16 h, l; splitf(y, h, l);
        g_yh[(ll)row * D + c] = h; g_yl[(ll)row * D + c] = l;
    }
}

// ---------------- RoPE + scale -> bf16 hi/lo ----------------
__global__ void rope_k() {
    int idx = blockIdx.x * 256 + threadIdx.x;
    if (idx >= NTOK * (D / 2)) return;
    int tok = idx / (D / 2);
    int p   = idx % (D / 2);
    int h = p >> 6;
    int j = p & 63;
    int s = tok & (S - 1);
    float freq = powf(10000.f, -(float)(2 * j) * (1.f / 128.f));
    float ang = (float)s * freq;
    float c, sn; sincosf(ang, &sn, &c);
    const float sc = 0.29730177875068026f;  // 128^-0.25
    ll base = (ll)tok * D + h * 128 + 2 * j;
    float qr = g_q[base], qi = g_q[base + 1];
    float q0 = (qr * c - qi * sn) * sc;
    float q1 = (qr * sn + qi * c) * sc;
    bf16 hh, lll;
    splitf(q0, hh, lll); g_qh[base] = hh;     g_ql[base] = lll;
    splitf(q1, hh, lll); g_qh[base + 1] = hh; g_ql[base + 1] = lll;
    float kr = g_k[base], ki = g_k[base + 1];
    float k0 = (kr * c - ki * sn) * sc;
    float k1 = (kr * sn + ki * c) * sc;
    splitf(k0, hh, lll); g_kh[base] = hh;     g_kl[base] = lll;
    splitf(k1, hh, lll); g_kh[base + 1] = hh; g_kl[base + 1] = lll;
}

// ---------------- masked softmax -> bf16 hi/lo probs ----------------
__global__ void softmax_k(const int* __restrict__ x_len) {
    ll row = blockIdx.x;
    int b = (int)(row >> 13);
    const float* r = g_scores + row * S;
    int tid = threadIdx.x;
    int xl = x_len[b];
    __shared__ float red[256];
    float v[4];
    #pragma unroll
    for (int i = 0; i < 4; i++) {
        int j = tid + 256 * i;
        float bias = (4 * j + 3 < xl) ? 0.f : -1e10f;
        v[i] = r[j] + bias;
    }
    float m = fmaxf(fmaxf(v[0], v[1]), fmaxf(v[2], v[3]));
    red[tid] = m; __syncthreads();
    for (int o = 128; o > 0; o >>= 1) { if (tid < o) red[tid] = fmaxf(red[tid], red[tid + o]); __syncthreads(); }
    m = red[0]; __syncthreads();
    float s = 0.f;
    #pragma unroll
    for (int i = 0; i < 4; i++) { v[i] = expf(v[i] - m); s += v[i]; }
    red[tid] = s; __syncthreads();
    for (int o = 128; o > 0; o >>= 1) { if (tid < o) red[tid] += red[tid + o]; __syncthreads(); }
    float inv = 1.f / red[0];
    #pragma unroll
    for (int i = 0; i < 4; i++) {
        float pv = v[i] * inv;
        bf16 h, l; splitf(pv, h, l);
        g_ph[row * S + tid + 256 * i] = h;
        g_pl[row * S + tid + 256 * i] = l;
    }
}

// ---------------- output ----------------
__global__ void out_k(float* __restrict__ out, const int* __restrict__ x_len, ll out_size) {
    ll i = (ll)blockIdx.x * 256 + threadIdx.x;
    const ll nh = (ll)NTOK * D;
    if (i < nh && i < out_size) out[i] = g_x[i];
    if (i < Bn) {
        ll pos = nh + i;
        if (pos < out_size) {
            int yl = (x_len[i] + 1) / 2;
            yl = (yl + 1) / 2;
            out[pos] = (float)yl;
        }
    }
}

// ---------------- host launcher ----------------
extern "C" void kernel_launch(void* const* d_in, const int* in_sizes, int n_in,
                              void* d_out, int out_size) {
    const float* x        = (const float*)d_in[0];
    const int*   x_len    = (const int*)  d_in[1];
    const float* conv1_w  = (const float*)d_in[2];
    const float* conv1_b  = (const float*)d_in[3];
    const float* conv2_w  = (const float*)d_in[4];
    const float* conv2_b  = (const float*)d_in[5];
    const float* attn_ln_w= (const float*)d_in[6];
    const float* attn_ln_b= (const float*)d_in[7];
    const float* q_w      = (const float*)d_in[8];
    const float* q_b      = (const float*)d_in[9];
    const float* k_w      = (const float*)d_in[10];
    const float* v_w      = (const float*)d_in[11];
    const float* v_b      = (const float*)d_in[12];
    const float* out_w    = (const float*)d_in[13];
    const float* out_b    = (const float*)d_in[14];
    const float* mlp_ln_w = (const float*)d_in[15];
    const float* mlp_ln_b = (const float*)d_in[16];
    const float* mlp1_w   = (const float*)d_in[17];
    const float* mlp1_b   = (const float*)d_in[18];
    const float* mlp2_w   = (const float*)d_in[19];
    const float* mlp2_b   = (const float*)d_in[20];

    static bool smemSet = false;
    cudaFuncSetAttribute(gemm_tc, cudaFuncAttributeMaxDynamicSharedMemorySize, 2 * STG_B);
    (void)smemSet;

    #define SYM(p, s) do { void* _t; cudaGetSymbolAddress(&_t, s); p = (decltype(p))_t; } while (0)
    float *h1, *xs, *qs, *ks, *sc;
    SYM(h1, g_h1); SYM(xs, g_x); SYM(qs, g_q); SYM(ks, g_k); SYM(sc, g_scores);
    bf16 *pc1h,*pc1l,*pc2h,*pc2l,*pwqh,*pwql,*pwkh,*pwkl,*pwvh,*pwvl,*pwoh,*pwol;
    bf16 *pw1h,*pw1l,*pw2h,*pw2l,*pcolh,*pcoll,*pyh,*pyl,*pqh,*pql,*pkh,*pkl;
    bf16 *pvth,*pvtl,*pph,*ppl,*pm1h,*pm1l,*poh,*pol;
    SYM(pc1h, c1h); SYM(pc1l, c1l); SYM(pc2h, c2h); SYM(pc2l, c2l);
    SYM(pwqh, wqh); SYM(pwql, wql); SYM(pwkh, wkh); SYM(pwkl, wkl);
    SYM(pwvh, wvh); SYM(pwvl, wvl); SYM(pwoh, woh); SYM(pwol, wol);
    SYM(pw1h, w1h); SYM(pw1l, w1l); SYM(pw2h, w2h); SYM(pw2l, w2l);
    SYM(pcolh, g_colh); SYM(pcoll, g_coll); SYM(pyh, g_yh); SYM(pyl, g_yl);
    SYM(pqh, g_qh); SYM(pql, g_ql); SYM(pkh, g_kh); SYM(pkl, g_kl);
    SYM(pvth, g_vth); SYM(pvtl, g_vtl); SYM(pph, g_ph); SYM(ppl, g_pl);
    SYM(pm1h, g_m1h); SYM(pm1l, g_m1l); SYM(poh, g_oh); SYM(pol, g_ol);

    auto split = [&](const float* in, bf16* hi, bf16* lo, ll n) {
        split_k<<<(int)((n / 4 + 255) / 256), 256>>>(in, hi, lo, n);
    };
    split(conv1_w, pc1h, pc1l, (ll)D * 384);
    split(conv2_w, pc2h, pc2l, (ll)D * 3072);
    split(q_w,   pwqh, pwql, (ll)Ldim * D * D);
    split(k_w,   pwkh, pwkl, (ll)Ldim * D * D);
    split(v_w,   pwvh, pwvl, (ll)Ldim * D * D);
    split(out_w, pwoh, pwol, (ll)Ldim * D * D);
    split(mlp1_w, pw1h, pw1l, (ll)Ldim * Fdim * D);
    split(mlp2_w, pw2h, pw2l, (ll)Ldim * Fdim * D);

    auto gemm = [&](const bf16* Ah, const bf16* Al, const bf16* Bh, const bf16* Bl,
                    float* C, bf16* Ch, bf16* Cl, const float* bias,
                    int M, int N, int K, int lda, int ldb, int ldc,
                    int nz, int zDiv,
                    ll sAo, ll sAi, ll sBo, ll sBi, ll sCo, ll sCi,
                    int biasMode, int addC, int act, int transStore,
                    int outF32, int outBf) {
        GemmP p;
        p.Ah = Ah; p.Al = Al; p.Bh = Bh; p.Bl = Bl;
        p.C = C; p.Ch = Ch; p.Cl = Cl; p.bias = bias;
        p.K = K; p.lda = lda; p.ldb = ldb; p.ldc = ldc;
        p.zDiv = zDiv;
        p.sAo = sAo; p.sAi = sAi; p.sBo = sBo; p.sBi = sBi; p.sCo = sCo; p.sCi = sCi;
        p.biasMode = biasMode; p.addC = addC; p.act = act;
        p.transStore = transStore; p.outF32 = outF32; p.outBf = outBf;
        dim3 g(N / 128, M / 128, nz);
        gemm_tc<<<g, 256, 2 * STG_B>>>(p);
    };

    const ll SD = (ll)S * D;
    const ll SS = (ll)S * S;

    // conv1
    im2col1_k<<<(Bn * T1 * 384 + 255) / 256, 256>>>(x);
    gemm(pc1h, pc1l, pcolh, pcoll, h1, 0, 0, conv1_b,
         1024, T1, 384, 384, 384, T1,
         Bn, 1, 0, 0, (ll)T1 * 384, 0, (ll)D * T1, 0,
         2, 0, 1, 0, 1, 0);

    // conv2 (transposed store -> residual stream g_x[tok][D])
    im2col2_k<<<(int)(((ll)Bn * S * 3072 + 255) / 256), 256>>>();
    gemm(pc2h, pc2l, pcolh, pcoll, xs, 0, 0, conv2_b,
         1024, S, 3072, 3072, 3072, D,
         Bn, 1, 0, 0, (ll)S * 3072, 0, SD, 0,
         2, 0, 1, 1, 1, 0);

    for (int l = 0; l < 6; l++) {
        const float* aw = attn_ln_w + l * D;  const float* ab = attn_ln_b + l * D;
        const float* qb = q_b + l * D;
        const float* vb = v_b + l * D;
        const float* ob = out_b + l * D;
        const float* mw = mlp_ln_w + l * D;   const float* mb = mlp_ln_b + l * D;
        const float* b1 = mlp1_b + l * Fdim;
        const float* b2 = mlp2_b + l * D;
        ll wOff = (ll)l * D * D;
        ll mOff = (ll)l * Fdim * D;

        ln_k<<<NTOK, 256>>>(xs, aw, ab);

        // q, k -> fp32 (RoPE splits them); v -> bf16 transposed [d][tok]
        gemm(pyh, pyl, pwqh + wOff, pwql + wOff, qs, 0, 0, qb,
             NTOK, D, D, D, D, D, 1, 1, 0,0,0,0,0,0, 1, 0, 0, 0, 1, 0);
        gemm(pyh, pyl, pwkh + wOff, pwkl + wOff, ks, 0, 0, 0,
             NTOK, D, D, D, D, D, 1, 1, 0,0,0,0,0,0, 0, 0, 0, 0, 1, 0);
        gemm(pyh, pyl, pwvh + wOff, pwvl + wOff, 0, pvth, pvtl, vb,
             NTOK, D, D, D, D, NTOK, 1, 1, 0,0,0,0,0,0, 1, 0, 0, 1, 0, 1);

        rope_k<<<(NTOK * (D / 2) + 255) / 256, 256>>>();

        // scores[b,h] = q_bh [S,128] @ k_bh^T
        gemm(pqh, pql, pkh, pkl, sc, 0, 0, 0,
             S, S, DH, D, D, S,
             Bn * H, H, SD, 128, SD, 128, (ll)H * SS, SS,
             0, 0, 0, 0, 1, 0);

        softmax_k<<<Bn * H * S, 256>>>(x_len);

        // o[b,h] = probs [S,S] @ vT_bh^T   (vT[d][tok] rows are the NT B operand)
        gemm(pph, ppl, pvth, pvtl, 0, poh, pol, 0,
             S, DH, S, S, NTOK, D,
             Bn * H, H, (ll)H * SS, SS, S, (ll)128 * NTOK, SD, 128,
             0, 0, 0, 0, 0, 1);

        // out projection + residual
        gemm(poh, pol, pwoh + wOff, pwol + wOff, xs, 0, 0, ob,
             NTOK, D, D, D, D, D, 1, 1, 0,0,0,0,0,0, 1, 1, 0, 0, 1, 0);

        // MLP
        ln_k<<<NTOK, 256>>>(xs, mw, mb);
        gemm(pyh, pyl, pw1h + mOff, pw1l + mOff, 0, pm1h, pm1l, b1,
             NTOK, Fdim, D, D, D, Fdim, 1, 1, 0,0,0,0,0,0, 1, 0, 1, 0, 0, 1);
        gemm(pm1h, pm1l, pw2h + mOff, pw2l + mOff, xs, 0, 0, b2,
             NTOK, D, Fdim, Fdim, Fdim, D, 1, 1, 0,0,0,0,0,0, 1, 1, 0, 0, 1, 0);
    }

    ll nh = (ll)NTOK * D;
    out_k<<<(int)((nh + 255) / 256), 256>>>((float*)d_out, x_len, (ll)out_size);
}